// round 3
// baseline (speedup 1.0000x reference)
#include <cuda_runtime.h>
#include <cuda_bf16.h>
#include <cstdint>

#define V      12288
#define E      128
#define NTI    96
#define NTILES (NTI * NTI)      // 9216
#define GRID   304              // 2 CTAs per SM (152 SMs)
#define SSTR   152              // smem row stride in bf16 elems (144 + 8 pad)
#define KEXT   144              // K extended for fused biases
#define SMEM_BYTES (2 * 128 * SSTR * 2)   // 77824

// ---------------------------------------------------------------------------
__device__ __nv_bfloat16 g_ctx[V * E];
__device__ __nv_bfloat16 g_tgt[V * E];

__global__ void convert_kernel(const float* __restrict__ tgt,
                               const float* __restrict__ ctx,
                               float* __restrict__ out) {
    if (blockIdx.x == 0 && threadIdx.x == 0) out[0] = 0.0f;
    int t = blockIdx.x * blockDim.x + threadIdx.x;
    int base = t * 8;
    if (base >= V * E) return;
    float4 a0 = *(const float4*)(tgt + base);
    float4 a1 = *(const float4*)(tgt + base + 4);
    float4 b0 = *(const float4*)(ctx + base);
    float4 b1 = *(const float4*)(ctx + base + 4);
    __nv_bfloat162 ta[4], ca[4];
    ta[0] = __floats2bfloat162_rn(a0.x, a0.y); ta[1] = __floats2bfloat162_rn(a0.z, a0.w);
    ta[2] = __floats2bfloat162_rn(a1.x, a1.y); ta[3] = __floats2bfloat162_rn(a1.z, a1.w);
    ca[0] = __floats2bfloat162_rn(b0.x, b0.y); ca[1] = __floats2bfloat162_rn(b0.z, b0.w);
    ca[2] = __floats2bfloat162_rn(b1.x, b1.y); ca[3] = __floats2bfloat162_rn(b1.z, b1.w);
    *(uint4*)(g_tgt + base) = *(const uint4*)ta;
    *(uint4*)(g_ctx + base) = *(const uint4*)ca;
}

// ---------------------------------------------------------------------------
__device__ __forceinline__ uint32_t smem_u32(const void* p) {
    uint32_t a;
    asm("{ .reg .u64 t; cvta.to.shared.u64 t, %1; cvt.u32.u64 %0, t; }" : "=r"(a) : "l"(p));
    return a;
}

__device__ __forceinline__ void mma_bf16(float c[4], const uint32_t a[4],
                                         const uint32_t b[2]) {
    asm volatile(
        "mma.sync.aligned.m16n8k16.row.col.f32.bf16.bf16.f32 "
        "{%0,%1,%2,%3}, {%4,%5,%6,%7}, {%8,%9}, {%0,%1,%2,%3};\n"
        : "+f"(c[0]), "+f"(c[1]), "+f"(c[2]), "+f"(c[3])
        : "r"(a[0]), "r"(a[1]), "r"(a[2]), "r"(a[3]), "r"(b[0]), "r"(b[1]));
}

#define CP_COMMIT() asm volatile("cp.async.commit_group;" ::: "memory")
#define CP_WAIT0()  asm volatile("cp.async.wait_group 0;" ::: "memory")

// ---------------------------------------------------------------------------
// A tile: plain staging (rare). cols 0..127 data, col 128=1.0, col 129=cb.
// cols 130..143 pre-zeroed once at kernel start.
// ---------------------------------------------------------------------------
__device__ __forceinline__ void stage_A(__nv_bfloat16* As, int bi,
                                        const float* __restrict__ cb, int tid) {
    const __nv_bfloat16* src = g_ctx + (size_t)bi * 128 * E;
    #pragma unroll
    for (int u = tid; u < 128 * 16; u += 256) {
        int row = u >> 4, part = u & 15;
        *(uint4*)(As + row * SSTR + part * 8) = *(const uint4*)(src + row * E + part * 8);
    }
    if (tid < 128) {
        uint32_t b = (uint32_t)__bfloat16_as_ushort(__float2bfloat16(cb[bi * 128 + tid]));
        *(uint32_t*)(As + tid * SSTR + 128) = 0x3F80u | (b << 16);   // (1.0, cb)
    }
}

// B tile: cp.async data cols 0..127; STS bias (tb, 1.0) at cols 128..129.
__device__ __forceinline__ void stage_B_async(uint32_t bs_u32, __nv_bfloat16* Bs,
                                              int bj, const float* __restrict__ tb,
                                              int tid) {
    const __nv_bfloat16* src = g_tgt + (size_t)bj * 128 * E;
    #pragma unroll
    for (int u = tid; u < 128 * 16; u += 256) {
        int row = u >> 4, part = u & 15;
        uint32_t dst = bs_u32 + (uint32_t)(row * (SSTR * 2) + part * 16);
        size_t gsrc = __cvta_generic_to_global(src + row * E + part * 8);
        asm volatile("cp.async.cg.shared.global [%0], [%1], 16;"
                     :: "r"(dst), "l"(gsrc) : "memory");
    }
    if (tid < 128) {
        uint32_t b = (uint32_t)__bfloat16_as_ushort(__float2bfloat16(tb[bj * 128 + tid]));
        *(uint32_t*)(Bs + tid * SSTR + 128) = b | (0x3F80u << 16);   // (tb, 1.0)
    }
}

// ---------------------------------------------------------------------------
// One GEMM pass: warp computes 32 (M) x 32 (N) using 9 k-steps of K=16.
// acc[mt][nt][4]: mt in {0,1} (16-row halves), nt in {0..3} (8-col strips).
// ---------------------------------------------------------------------------
__device__ __forceinline__ void gemm_pass(const __nv_bfloat16* __restrict__ As,
                                          const __nv_bfloat16* __restrict__ Bs,
                                          int m0, int n0, int g, int tig,
                                          float acc[2][4][4]) {
    #pragma unroll
    for (int mt = 0; mt < 2; mt++)
        #pragma unroll
        for (int nt = 0; nt < 4; nt++)
            #pragma unroll
            for (int r = 0; r < 4; r++) acc[mt][nt][r] = 0.0f;

    #pragma unroll
    for (int ko = 0; ko < KEXT; ko += 16) {
        uint32_t afr[2][4];
        #pragma unroll
        for (int mt = 0; mt < 2; mt++) {
            const __nv_bfloat16* ap = As + (m0 + mt * 16 + g) * SSTR + ko + 2 * tig;
            afr[mt][0] = *(const uint32_t*)(ap);
            afr[mt][1] = *(const uint32_t*)(ap + 8 * SSTR);
            afr[mt][2] = *(const uint32_t*)(ap + 8);
            afr[mt][3] = *(const uint32_t*)(ap + 8 * SSTR + 8);
        }
        uint32_t bfr[4][2];
        #pragma unroll
        for (int nt = 0; nt < 4; nt++) {
            const __nv_bfloat16* bp = Bs + (n0 + nt * 8 + g) * SSTR + ko + 2 * tig;
            bfr[nt][0] = *(const uint32_t*)(bp);
            bfr[nt][1] = *(const uint32_t*)(bp + 8);
        }
        #pragma unroll
        for (int mt = 0; mt < 2; mt++)
            #pragma unroll
            for (int nt = 0; nt < 4; nt++)
                mma_bf16(acc[mt][nt], afr[mt], bfr[nt]);
    }
}

// ---------------------------------------------------------------------------
// Epilogue pass: 32x32 warp subtile. acc already contains dots + tb + cb.
// ---------------------------------------------------------------------------
__device__ __forceinline__ void epi_pass(const float* __restrict__ X,
                                         int i0, int jw, int g, int tig,
                                         float acc[2][4][4], float& lsum) {
    #pragma unroll
    for (int mt = 0; mt < 2; mt++) {
        #pragma unroll
        for (int h = 0; h < 2; h++) {
            const int i = i0 + mt * 16 + h * 8 + g;
            const float2* xr = (const float2*)(X + (size_t)i * V + jw) + tig;
            float2 xv[4];
            #pragma unroll
            for (int nt = 0; nt < 4; nt++) xv[nt] = __ldcs(xr + nt * 4);
            #pragma unroll
            for (int nt = 0; nt < 4; nt++) {
                {
                    float x = xv[nt].x;
                    float d = acc[mt][nt][h * 2 + 0] - __logf(1.0f + x);
                    float w = fminf(__powf(x * 0.01f, 0.75f), 1.0f);
                    lsum = fmaf(w * d, d, lsum);
                }
                {
                    float x = xv[nt].y;
                    float d = acc[mt][nt][h * 2 + 1] - __logf(1.0f + x);
                    float w = fminf(__powf(x * 0.01f, 0.75f), 1.0f);
                    lsum = fmaf(w * d, d, lsum);
                }
            }
        }
    }
}

// ---------------------------------------------------------------------------
// Persistent fused kernel. 304 CTAs x 256 threads (2 CTA/SM).
// Per tile: GEMM p0 -> epi p0 -> GEMM p1 -> sync -> prefetch B(t+1) (+A if
// row band changes) -> epi p1 (overlaps prefetch) -> wait -> sync.
// ---------------------------------------------------------------------------
__global__ void __launch_bounds__(256, 2)
glove_mma(const float* __restrict__ X,
          const float* __restrict__ tb,
          const float* __restrict__ cb,
          float* __restrict__ out) {
    extern __shared__ __nv_bfloat16 smem[];
    __nv_bfloat16* As = smem;
    __nv_bfloat16* Bs = smem + 128 * SSTR;
    __shared__ float red[8];

    const int tid  = threadIdx.x;
    const int warp = tid >> 5;
    const int lane = tid & 31;
    const int wm   = warp >> 1;
    const int wn   = warp & 1;
    const int g    = lane >> 2;
    const int tig  = lane & 3;
    const uint32_t bs_u32 = smem_u32(Bs);

    // Pre-zero bias pad (cols 128..143) of both tiles once.
    if (tid < 128) {
        uint4 z = make_uint4(0u, 0u, 0u, 0u);
        *(uint4*)(As + tid * SSTR + 128) = z;
        *(uint4*)(As + tid * SSTR + 136) = z;
        *(uint4*)(Bs + tid * SSTR + 128) = z;
        *(uint4*)(Bs + tid * SSTR + 136) = z;
    }
    __syncthreads();

    const int per = NTILES / GRID, rem = NTILES % GRID;
    const int bidx = blockIdx.x;
    const int start = bidx * per + (bidx < rem ? bidx : rem);
    const int cnt = per + (bidx < rem ? 1 : 0);

    // Prologue: stage A and B for the first tile.
    int bi = start / NTI;
    {
        const int bj0 = start - bi * NTI;
        stage_A(As, bi, cb, tid);
        stage_B_async(bs_u32, Bs, bj0, tb, tid);
        CP_COMMIT();
        CP_WAIT0();
        __syncthreads();
    }

    float lsum = 0.0f;
    float acc[2][4][4];

    for (int it = 0; it < cnt; ++it) {
        const int t  = start + it;
        const int cbi = t / NTI;           // == bi (A already staged)
        const int cbj = t - cbi * NTI;
        const int m0 = wm * 32;
        const int i0 = cbi * 128 + m0;

        // pass 0 (cols wn*64 .. wn*64+31)
        gemm_pass(As, Bs, m0, wn * 64, g, tig, acc);
        epi_pass(X, i0, cbj * 128 + wn * 64, g, tig, acc, lsum);

        // pass 1 (cols wn*64+32 .. wn*64+63)
        gemm_pass(As, Bs, m0, wn * 64 + 32, g, tig, acc);
        __syncthreads();                    // all warps done reading As/Bs

        if (it + 1 < cnt) {                 // prefetch next tile
            const int nt_ = t + 1;
            const int nbi = nt_ / NTI, nbj = nt_ - nbi * NTI;
            if (nbi != bi) { stage_A(As, nbi, cb, tid); bi = nbi; }
            stage_B_async(bs_u32, Bs, nbj, tb, tid);
            CP_COMMIT();
        }

        epi_pass(X, i0, cbj * 128 + wn * 64 + 32, g, tig, acc, lsum);

        CP_WAIT0();
        __syncthreads();
    }

    // Reduction: one atomic per CTA.
    #pragma unroll
    for (int off = 16; off; off >>= 1) lsum += __shfl_xor_sync(0xFFFFFFFFu, lsum, off);
    if (lane == 0) red[warp] = lsum;
    __syncthreads();
    if (tid == 0) {
        float s = 0.0f;
        #pragma unroll
        for (int w = 0; w < 8; ++w) s += red[w];
        atomicAdd(out, s);
    }
}

// ---------------------------------------------------------------------------
extern "C" void kernel_launch(void* const* d_in, const int* in_sizes, int n_in,
                              void* d_out, int out_size) {
    const float* X   = (const float*)d_in[0];
    const float* te  = (const float*)d_in[1];
    const float* ce  = (const float*)d_in[2];
    const float* tbp = (const float*)d_in[3];
    const float* cbp = (const float*)d_in[4];
    float* out = (float*)d_out;

    static bool attr_set = false;
    if (!attr_set) {
        cudaFuncSetAttribute(glove_mma, cudaFuncAttributeMaxDynamicSharedMemorySize,
                             SMEM_BYTES);
        attr_set = true;
    }

    const int conv_threads = V * E / 8;
    convert_kernel<<<(conv_threads + 255) / 256, 256>>>(te, ce, out);
    glove_mma<<<GRID, 256, SMEM_BYTES>>>(X, tbp, cbp, out);
    (void)in_sizes; (void)n_in; (void)out_size;
}